// round 5
// baseline (speedup 1.0000x reference)
#include <cuda_runtime.h>
#include <cuda_bf16.h>
#include <cstdint>

// ===========================================================================
// Kagome conv as implicit GEMM on mma.sync (bf16 hi/lo 3-pass, fp32 accum).
// R5: ci chunked 2x64 -> image tile 104KB; W staged per-tap into smem via
// cp.async double buffering (hides the 234-260cyc L2 latency that capped
// tensor pipe at 57% in R4). Hot loop reads W via LDS.128.
// ===========================================================================

__constant__ int FDR[37] = {1,1,2,3,4,4,6,7,8,10,11,12,14,14,15,16,17,17,16,15,14,14,12,10,8,6,4,4,3,2,5,9,13,15,17,15,13};
__constant__ int FDC[37] = {3,5,7,9,10,11,13,13,14,15,15,16,15,16,15,14,13,11,9,7,6,5,3,2,1,0,0,1,1,2,0,2,4,8,12,14,16};
__constant__ int FSR[37] = {13,13,14,15,16,16,6,7,8,10,11,12,2,2,3,4,5,5,4,3,2,2,12,10,8,6,16,16,15,14,5,9,1,3,5,3,1};
__constant__ int FSC[37] = {15,5,7,9,10,11,1,1,2,3,3,4,3,4,3,2,1,11,9,7,6,5,15,14,13,12,12,13,13,14,12,14,4,8,12,2,4};

__constant__ unsigned MASKROW[16] = {
    0x0008u, 0x003Cu, 0x00FEu, 0x01FEu,
    0x0FFFu, 0x0FFFu, 0x0FFFu, 0x1FFEu,
    0x3FFCu, 0x3FFCu, 0x3FFCu, 0x7FF8u,
    0x7FF0u, 0x3FC0u, 0x1F00u, 0x1E00u
};

// W split+permuted: [tap][co][ci_perm], u32 = bf16hi | bf16lo<<16
__device__ unsigned int Wt[9][128][128];

#define IPAD 80        // image row stride (u32); 80%32==16 -> conflict-free LDS.128
#define WPAD 80        // W row stride (u32)
#define IMG_U32  (324 * IPAD)            // 25920 u32 = 103680 B
#define WBUF_U32 (128 * WPAD)            // 10240 u32 = 40960 B
#define SMEM_BYTES ((IMG_U32 + 2 * WBUF_U32) * 4)   // 185600 B

static __device__ __forceinline__ uint32_t pack_hl(float v) {
    __nv_bfloat16 h = __float2bfloat16(v);
    float hv = __bfloat162float(h);
    __nv_bfloat16 l = __float2bfloat16(v - hv);
    return (uint32_t)__bfloat16_as_ushort(h) |
           ((uint32_t)__bfloat16_as_ushort(l) << 16);
}

// slot within a 16-ci group: quad q owns u32 slots 4q..4q+3 = k {2q,2q+1,2q+8,2q+9}
static __device__ __forceinline__ int slot16(int k) {
    return ((k & 7) >> 1) * 4 + (k & 1) + ((k >> 3) << 1);
}

static __device__ __forceinline__ void mma_bf16(float* c, const uint32_t* a,
                                                uint32_t b0, uint32_t b1) {
    asm volatile(
        "mma.sync.aligned.m16n8k16.row.col.f32.bf16.bf16.f32 "
        "{%0,%1,%2,%3}, {%4,%5,%6,%7}, {%8,%9}, {%0,%1,%2,%3};"
        : "+f"(c[0]), "+f"(c[1]), "+f"(c[2]), "+f"(c[3])
        : "r"(a[0]), "r"(a[1]), "r"(a[2]), "r"(a[3]), "r"(b0), "r"(b1));
}

// issue one tap's W tile (128 co x 64 ci u32) into a smem buffer + commit
static __device__ __forceinline__ void prefetch_w(uint32_t* wbuf, int tap,
                                                  int cb, int tid) {
    #pragma unroll
    for (int i = 0; i < 4; i++) {
        int idx = tid + i * 512;           // 0..2047
        int co = idx >> 4, ch = idx & 15;  // 16B chunk within 64 u32
        uint32_t dst = (uint32_t)__cvta_generic_to_shared(wbuf + co * WPAD + ch * 4);
        const void* src = &Wt[tap][co][cb + ch * 4];
        asm volatile("cp.async.cg.shared.global [%0], [%1], 16;"
                     :: "r"(dst), "l"(src));
    }
    asm volatile("cp.async.commit_group;" ::: "memory");
}

// ---------------- prep: W -> Wt[tap][co][ci_perm] ----------------
__global__ void prep_w_kernel(const float* __restrict__ W) {
    int idx = blockIdx.x * 256 + threadIdx.x;
    if (idx >= 9 * 128 * 128) return;
    int tap = idx >> 14;
    int co  = (idx >> 7) & 127;
    int ci  = idx & 127;
    uint32_t p = pack_hl(W[co * 1152 + ci * 9 + tap]);
    Wt[tap][co][(ci >> 4) * 16 + slot16(ci & 15)] = p;
}

// ---------------- main ----------------
__global__ void __launch_bounds__(512, 1)
kagome_mma_kernel(const float* __restrict__ x,
                  const float* __restrict__ b,
                  float* __restrict__ out) {
    extern __shared__ uint32_t smu[];
    uint32_t* xp2 = smu;                 // [324 pos][IPAD]
    uint32_t* wb  = smu + IMG_U32;       // 2 x [128 co][WPAD]

    const int tid   = threadIdx.x;
    const int wid   = tid >> 5;
    const int lane  = tid & 31;
    const int q     = lane & 3;
    const int lr    = lane >> 2;
    const int warpM = wid & 3;
    const int warpN = wid >> 2;
    const int img   = blockIdx.x;

    const float* xg = x + (size_t)img * 128 * 256;

    float C[4][4][4];
    #pragma unroll
    for (int s = 0; s < 4; s++)
        #pragma unroll
        for (int n = 0; n < 4; n++)
            #pragma unroll
            for (int e = 0; e < 4; e++) C[s][n][e] = 0.f;

    int buf = 0;
    for (int cb = 0; cb < 128; cb += 64) {
        __syncthreads();   // prior chunk's reads done before restaging

        // zero image tile (borders must be 0)
        {
            uint4* z = (uint4*)xp2;
            #pragma unroll
            for (int i = 0; i < 13; i++) {
                int j = tid + i * 512;
                if (j < IMG_U32 / 4) z[j] = make_uint4(0, 0, 0, 0);
            }
        }
        __syncthreads();
        // interior: 64 ci x 256 px
        #pragma unroll
        for (int i = 0; i < 32; i++) {
            int idx = tid + i * 512;
            int ci = idx >> 8, px = idx & 255;
            uint32_t p = pack_hl(xg[(cb + ci) * 256 + px]);
            int pos = ((px >> 4) + 1) * 18 + (px & 15) + 1;
            xp2[pos * IPAD + (ci >> 4) * 16 + slot16(ci & 15)] = p;
        }
        __syncthreads();   // interior visible before fixups overwrite
        for (int j = tid; j < 64 * 37; j += 512) {
            int ci = j / 37, f = j - ci * 37;
            uint32_t p = pack_hl(xg[(cb + ci) * 256 + (FSR[f] - 1) * 16 + (FSC[f] - 1)]);
            int pos = FDR[f] * 18 + FDC[f];
            xp2[pos * IPAD + (ci >> 4) * 16 + slot16(ci & 15)] = p;
        }
        // prefetch W for tap 0 of this chunk (pending groups: 1)
        prefetch_w(wb + buf * WBUF_U32, 0, cb, tid);
        __syncthreads();   // image staging visible

        for (int tap = 0; tap < 9; tap++) {
            const int kr = tap / 3, kc = tap - kr * 3;
            if (tap < 8) {
                prefetch_w(wb + (buf ^ 1) * WBUF_U32, tap + 1, cb, tid);
                asm volatile("cp.async.wait_group 1;" ::: "memory");
            } else {
                asm volatile("cp.async.wait_group 0;" ::: "memory");
            }
            __syncthreads();   // current W buffer visible to all warps

            const uint32_t* wcur = wb + buf * WBUF_U32;
            #pragma unroll
            for (int g = 0; g < 4; g++) {
                uint32_t ah[4][4], al[4][4];
                #pragma unroll
                for (int s = 0; s < 4; s++) {
                    int R = warpM * 4 + s;
                    int base = ((R + kr) * 18 + kc) * IPAD + g * 16 + q * 4;
                    uint4 v0 = *(const uint4*)(xp2 + base + lr * IPAD);
                    uint4 v1 = *(const uint4*)(xp2 + base + (lr + 8) * IPAD);
                    ah[s][0] = __byte_perm(v0.x, v0.y, 0x5410);
                    ah[s][2] = __byte_perm(v0.z, v0.w, 0x5410);
                    ah[s][1] = __byte_perm(v1.x, v1.y, 0x5410);
                    ah[s][3] = __byte_perm(v1.z, v1.w, 0x5410);
                    al[s][0] = __byte_perm(v0.x, v0.y, 0x7632);
                    al[s][2] = __byte_perm(v0.z, v0.w, 0x7632);
                    al[s][1] = __byte_perm(v1.x, v1.y, 0x7632);
                    al[s][3] = __byte_perm(v1.z, v1.w, 0x7632);
                }
                #pragma unroll
                for (int ns = 0; ns < 4; ns++) {
                    int co = warpN * 32 + ns * 8 + lr;
                    uint4 w = *(const uint4*)(wcur + co * WPAD + g * 16 + q * 4);
                    uint32_t bh0 = __byte_perm(w.x, w.y, 0x5410);
                    uint32_t bh1 = __byte_perm(w.z, w.w, 0x5410);
                    uint32_t bl0 = __byte_perm(w.x, w.y, 0x7632);
                    uint32_t bl1 = __byte_perm(w.z, w.w, 0x7632);
                    #pragma unroll
                    for (int s = 0; s < 4; s++) mma_bf16(C[s][ns], ah[s], bh0, bh1);
                    #pragma unroll
                    for (int s = 0; s < 4; s++) mma_bf16(C[s][ns], al[s], bh0, bh1);
                    #pragma unroll
                    for (int s = 0; s < 4; s++) mma_bf16(C[s][ns], ah[s], bl0, bl1);
                }
            }
            buf ^= 1;
            __syncthreads();   // all reads of old buffer done before next prefetch
        }
    }

    // ---- epilogue: +bias, *mask, store ----
    float* og = out + (size_t)img * 128 * 256;
    #pragma unroll
    for (int ns = 0; ns < 4; ns++) {
        int co0 = warpN * 32 + ns * 8 + 2 * q;
        float bv0 = __ldg(b + co0);
        float bv1 = __ldg(b + co0 + 1);
        #pragma unroll
        for (int s = 0; s < 4; s++) {
            int R = warpM * 4 + s;
            unsigned mrow = MASKROW[R];
            float k0 = ((mrow >> lr) & 1u) ? 1.f : 0.f;
            float k1 = ((mrow >> (lr + 8)) & 1u) ? 1.f : 0.f;
            int p0 = R * 16 + lr;
            int p1 = p0 + 8;
            og[co0 * 256 + p0]       = (C[s][ns][0] + bv0) * k0;
            og[(co0 + 1) * 256 + p0] = (C[s][ns][1] + bv1) * k0;
            og[co0 * 256 + p1]       = (C[s][ns][2] + bv0) * k1;
            og[(co0 + 1) * 256 + p1] = (C[s][ns][3] + bv1) * k1;
        }
    }
}

extern "C" void kernel_launch(void* const* d_in, const int* in_sizes, int n_in,
                              void* d_out, int out_size) {
    (void)in_sizes; (void)n_in; (void)out_size;
    const float* x = (const float*)d_in[0];
    const float* W = (const float*)d_in[1];
    const float* b = (const float*)d_in[2];
    float* out = (float*)d_out;

    cudaFuncSetAttribute(kagome_mma_kernel,
                         cudaFuncAttributeMaxDynamicSharedMemorySize, SMEM_BYTES);

    prep_w_kernel<<<(9 * 128 * 128 + 255) / 256, 256>>>(W);
    kagome_mma_kernel<<<2048, 512, SMEM_BYTES>>>(x, b, out);
}

// round 6
// speedup vs baseline: 1.0046x; 1.0046x over previous
#include <cuda_runtime.h>
#include <cuda_bf16.h>
#include <cstdint>

// ===========================================================================
// Kagome conv as implicit GEMM on mma.sync (bf16 hi/lo 3-pass, fp32 accum).
// R6: ci chunked 4x32. Per chunk, ALL 9 taps of W staged to smem (152KB) +
// image tile (61KB); compute runs 18 k-group iters with ZERO barriers and
// no LDG in the hot loop (R4's binder: 250cyc W LDG vs 96cyc of cover).
// Strides IPAD=48, WST=304 (both ==16 mod 32 u32): conflict-free LDS.128.
// ===========================================================================

__constant__ int FDR[37] = {1,1,2,3,4,4,6,7,8,10,11,12,14,14,15,16,17,17,16,15,14,14,12,10,8,6,4,4,3,2,5,9,13,15,17,15,13};
__constant__ int FDC[37] = {3,5,7,9,10,11,13,13,14,15,15,16,15,16,15,14,13,11,9,7,6,5,3,2,1,0,0,1,1,2,0,2,4,8,12,14,16};
__constant__ int FSR[37] = {13,13,14,15,16,16,6,7,8,10,11,12,2,2,3,4,5,5,4,3,2,2,12,10,8,6,16,16,15,14,5,9,1,3,5,3,1};
__constant__ int FSC[37] = {15,5,7,9,10,11,1,1,2,3,3,4,3,4,3,2,1,11,9,7,6,5,15,14,13,12,12,13,13,14,12,14,4,8,12,2,4};

__constant__ unsigned MASKROW[16] = {
    0x0008u, 0x003Cu, 0x00FEu, 0x01FEu,
    0x0FFFu, 0x0FFFu, 0x0FFFu, 0x1FFEu,
    0x3FFCu, 0x3FFCu, 0x3FFCu, 0x7FF8u,
    0x7FF0u, 0x3FC0u, 0x1F00u, 0x1E00u
};

// W split+permuted: [tap][co][ci_perm], u32 = bf16hi | bf16lo<<16
__device__ unsigned int Wt[9][128][128];

#define IPAD 48                       // image row stride u32 (48%32==16)
#define WST  304                      // W co stride u32 (9*32=288 + 16; 304%32==16)
#define IMG_U32  (324 * IPAD)         // 15552 u32 = 62208 B
#define WBUF_U32 (128 * WST)          // 38912 u32 = 155648 B
#define SMEM_BYTES ((IMG_U32 + WBUF_U32) * 4)   // 217,856 B

static __device__ __forceinline__ uint32_t pack_hl(float v) {
    __nv_bfloat16 h = __float2bfloat16(v);
    float hv = __bfloat162float(h);
    __nv_bfloat16 l = __float2bfloat16(v - hv);
    return (uint32_t)__bfloat16_as_ushort(h) |
           ((uint32_t)__bfloat16_as_ushort(l) << 16);
}

// slot within a 16-ci group: quad q owns u32 slots 4q..4q+3 = k {2q,2q+1,2q+8,2q+9}
static __device__ __forceinline__ int slot16(int k) {
    return ((k & 7) >> 1) * 4 + (k & 1) + ((k >> 3) << 1);
}

static __device__ __forceinline__ void mma_bf16(float* c, const uint32_t* a,
                                                uint32_t b0, uint32_t b1) {
    asm volatile(
        "mma.sync.aligned.m16n8k16.row.col.f32.bf16.bf16.f32 "
        "{%0,%1,%2,%3}, {%4,%5,%6,%7}, {%8,%9}, {%0,%1,%2,%3};"
        : "+f"(c[0]), "+f"(c[1]), "+f"(c[2]), "+f"(c[3])
        : "r"(a[0]), "r"(a[1]), "r"(a[2]), "r"(a[3]), "r"(b0), "r"(b1));
}

// ---------------- prep: W -> Wt[tap][co][ci_perm] ----------------
__global__ void prep_w_kernel(const float* __restrict__ W) {
    int idx = blockIdx.x * 256 + threadIdx.x;
    if (idx >= 9 * 128 * 128) return;
    int tap = idx >> 14;
    int co  = (idx >> 7) & 127;
    int ci  = idx & 127;
    uint32_t p = pack_hl(W[co * 1152 + ci * 9 + tap]);
    Wt[tap][co][(ci >> 4) * 16 + slot16(ci & 15)] = p;
}

// ---------------- main ----------------
__global__ void __launch_bounds__(512, 1)
kagome_mma_kernel(const float* __restrict__ x,
                  const float* __restrict__ b,
                  float* __restrict__ out) {
    extern __shared__ uint32_t smu[];
    uint32_t* xp2 = smu;               // [324 pos][IPAD]
    uint32_t* wb  = smu + IMG_U32;     // [128 co][WST]: tap*32 + kgrp*16 + slot

    const int tid   = threadIdx.x;
    const int wid   = tid >> 5;
    const int lane  = tid & 31;
    const int q     = lane & 3;
    const int lr    = lane >> 2;
    const int warpM = wid & 3;
    const int warpN = wid >> 2;
    const int img   = blockIdx.x;

    const float* xg = x + (size_t)img * 128 * 256;

    float C[4][4][4];
    #pragma unroll
    for (int s = 0; s < 4; s++)
        #pragma unroll
        for (int n = 0; n < 4; n++)
            #pragma unroll
            for (int e = 0; e < 4; e++) C[s][n][e] = 0.f;

    for (int cb = 0; cb < 128; cb += 32) {
        __syncthreads();   // prior chunk's compute done reading xp2/wb

        // issue W staging for this chunk: 9 taps x 128 co x 32 u32
        // 9216 x 16B transfers / 512 threads = 18 each
        #pragma unroll
        for (int i = 0; i < 18; i++) {
            int idx = tid + i * 512;
            int tap = idx >> 10;
            int rem = idx & 1023;
            int co = rem >> 3, ch = rem & 7;
            uint32_t dst = (uint32_t)__cvta_generic_to_shared(
                wb + co * WST + tap * 32 + ch * 4);
            const void* src = &Wt[tap][co][cb + ch * 4];
            asm volatile("cp.async.cg.shared.global [%0], [%1], 16;"
                         :: "r"(dst), "l"(src));
        }
        asm volatile("cp.async.commit_group;" ::: "memory");

        // zero image tile (borders must be 0)
        {
            uint4* z = (uint4*)xp2;
            #pragma unroll
            for (int i = 0; i < 8; i++) {
                int j = tid + i * 512;
                if (j < IMG_U32 / 4) z[j] = make_uint4(0, 0, 0, 0);
            }
        }
        __syncthreads();
        // interior: 32 ci x 256 px
        #pragma unroll
        for (int i = 0; i < 16; i++) {
            int idx = tid + i * 512;
            int ci = idx >> 8, px = idx & 255;
            uint32_t p = pack_hl(xg[(cb + ci) * 256 + px]);
            int pos = ((px >> 4) + 1) * 18 + (px & 15) + 1;
            xp2[pos * IPAD + (ci >> 4) * 16 + slot16(ci & 15)] = p;
        }
        __syncthreads();   // interior visible before fixups overwrite
        for (int j = tid; j < 32 * 37; j += 512) {
            int ci = j / 37, f = j - ci * 37;
            uint32_t p = pack_hl(xg[(cb + ci) * 256 + (FSR[f] - 1) * 16 + (FSC[f] - 1)]);
            int pos = FDR[f] * 18 + FDC[f];
            xp2[pos * IPAD + (ci >> 4) * 16 + slot16(ci & 15)] = p;
        }
        asm volatile("cp.async.wait_group 0;" ::: "memory");
        __syncthreads();   // staging + W visible; mainloop is barrier-free

        #pragma unroll 1
        for (int tap = 0; tap < 9; tap++) {
            const int kr = tap / 3, kc = tap - kr * 3;
            #pragma unroll
            for (int g = 0; g < 2; g++) {
                uint32_t ah[4][4], al[4][4];
                #pragma unroll
                for (int s = 0; s < 4; s++) {
                    int R = warpM * 4 + s;
                    int base = ((R + kr) * 18 + kc) * IPAD + g * 16 + q * 4;
                    uint4 v0 = *(const uint4*)(xp2 + base + lr * IPAD);
                    uint4 v1 = *(const uint4*)(xp2 + base + (lr + 8) * IPAD);
                    ah[s][0] = __byte_perm(v0.x, v0.y, 0x5410);
                    ah[s][2] = __byte_perm(v0.z, v0.w, 0x5410);
                    ah[s][1] = __byte_perm(v1.x, v1.y, 0x5410);
                    ah[s][3] = __byte_perm(v1.z, v1.w, 0x5410);
                    al[s][0] = __byte_perm(v0.x, v0.y, 0x7632);
                    al[s][2] = __byte_perm(v0.z, v0.w, 0x7632);
                    al[s][1] = __byte_perm(v1.x, v1.y, 0x7632);
                    al[s][3] = __byte_perm(v1.z, v1.w, 0x7632);
                }
                #pragma unroll
                for (int ns = 0; ns < 4; ns++) {
                    int co = warpN * 32 + ns * 8 + lr;
                    uint4 w = *(const uint4*)(wb + co * WST + tap * 32 + g * 16 + q * 4);
                    uint32_t bh0 = __byte_perm(w.x, w.y, 0x5410);
                    uint32_t bh1 = __byte_perm(w.z, w.w, 0x5410);
                    uint32_t bl0 = __byte_perm(w.x, w.y, 0x7632);
                    uint32_t bl1 = __byte_perm(w.z, w.w, 0x7632);
                    #pragma unroll
                    for (int s = 0; s < 4; s++) mma_bf16(C[s][ns], ah[s], bh0, bh1);
                    #pragma unroll
                    for (int s = 0; s < 4; s++) mma_bf16(C[s][ns], al[s], bh0, bh1);
                    #pragma unroll
                    for (int s = 0; s < 4; s++) mma_bf16(C[s][ns], ah[s], bl0, bl1);
                }
            }
        }
    }

    // ---- epilogue: +bias, *mask, store ----
    float* og = out + (size_t)img * 128 * 256;
    #pragma unroll
    for (int ns = 0; ns < 4; ns++) {
        int co0 = warpN * 32 + ns * 8 + 2 * q;
        float bv0 = __ldg(b + co0);
        float bv1 = __ldg(b + co0 + 1);
        #pragma unroll
        for (int s = 0; s < 4; s++) {
            int R = warpM * 4 + s;
            unsigned mrow = MASKROW[R];
            float k0 = ((mrow >> lr) & 1u) ? 1.f : 0.f;
            float k1 = ((mrow >> (lr + 8)) & 1u) ? 1.f : 0.f;
            int p0 = R * 16 + lr;
            int p1 = p0 + 8;
            og[co0 * 256 + p0]       = (C[s][ns][0] + bv0) * k0;
            og[(co0 + 1) * 256 + p0] = (C[s][ns][1] + bv1) * k0;
            og[co0 * 256 + p1]       = (C[s][ns][2] + bv0) * k1;
            og[(co0 + 1) * 256 + p1] = (C[s][ns][3] + bv1) * k1;
        }
    }
}

extern "C" void kernel_launch(void* const* d_in, const int* in_sizes, int n_in,
                              void* d_out, int out_size) {
    (void)in_sizes; (void)n_in; (void)out_size;
    const float* x = (const float*)d_in[0];
    const float* W = (const float*)d_in[1];
    const float* b = (const float*)d_in[2];
    float* out = (float*)d_out;

    cudaFuncSetAttribute(kagome_mma_kernel,
                         cudaFuncAttributeMaxDynamicSharedMemorySize, SMEM_BYTES);

    prep_w_kernel<<<(9 * 128 * 128 + 255) / 256, 256>>>(W);
    kagome_mma_kernel<<<2048, 512, SMEM_BYTES>>>(x, b, out);
}

// round 7
// speedup vs baseline: 1.0715x; 1.0666x over previous
#include <cuda_runtime.h>
#include <cuda_bf16.h>
#include <cstdint>

// ===========================================================================
// Kagome conv as implicit GEMM on mma.sync (bf16 hi/lo 3-pass, fp32 accum).
// R7 = R4 structure (single full-image staging, W via LDG.128) +
//   - pass-major mma ordering: same-C accumulator reuse distance 8 mma
//     (R4-R6 used C-major order, distance 4 mma ~= 32cyc ~ HMMA latency ->
//      per-pass serialization; the common binder across all three rounds)
//   - B fragments hoisted & resident per g-iter; s processed in halves of 2
//     to stay within 128 regs
//   - pad-ring-only zeroing of the image tile (68 cells, not 187KB)
// ===========================================================================

__constant__ int FDR[37] = {1,1,2,3,4,4,6,7,8,10,11,12,14,14,15,16,17,17,16,15,14,14,12,10,8,6,4,4,3,2,5,9,13,15,17,15,13};
__constant__ int FDC[37] = {3,5,7,9,10,11,13,13,14,15,15,16,15,16,15,14,13,11,9,7,6,5,3,2,1,0,0,1,1,2,0,2,4,8,12,14,16};
__constant__ int FSR[37] = {13,13,14,15,16,16,6,7,8,10,11,12,2,2,3,4,5,5,4,3,2,2,12,10,8,6,16,16,15,14,5,9,1,3,5,3,1};
__constant__ int FSC[37] = {15,5,7,9,10,11,1,1,2,3,3,4,3,4,3,2,1,11,9,7,6,5,15,14,13,12,12,13,13,14,12,14,4,8,12,2,4};

__constant__ unsigned MASKROW[16] = {
    0x0008u, 0x003Cu, 0x00FEu, 0x01FEu,
    0x0FFFu, 0x0FFFu, 0x0FFFu, 0x1FFEu,
    0x3FFCu, 0x3FFCu, 0x3FFCu, 0x7FF8u,
    0x7FF0u, 0x3FC0u, 0x1F00u, 0x1E00u
};

// W split+permuted: [tap][co][ci_perm], u32 = bf16hi | bf16lo<<16
__device__ unsigned int Wt[9][128][128];

#define PAD 144                      // u32 per pos-row; conflict-free LDS.128
#define SMEM_BYTES (324 * PAD * 4)   // 186,624 B

static __device__ __forceinline__ uint32_t pack_hl(float v) {
    __nv_bfloat16 h = __float2bfloat16(v);
    float hv = __bfloat162float(h);
    __nv_bfloat16 l = __float2bfloat16(v - hv);
    return (uint32_t)__bfloat16_as_ushort(h) |
           ((uint32_t)__bfloat16_as_ushort(l) << 16);
}

// slot within a 16-ci group: quad q owns u32 slots 4q..4q+3 = k {2q,2q+1,2q+8,2q+9}
static __device__ __forceinline__ int slot16(int k) {
    return ((k & 7) >> 1) * 4 + (k & 1) + ((k >> 3) << 1);
}

static __device__ __forceinline__ void mma_bf16(float* c, const uint32_t* a,
                                                uint32_t b0, uint32_t b1) {
    asm volatile(
        "mma.sync.aligned.m16n8k16.row.col.f32.bf16.bf16.f32 "
        "{%0,%1,%2,%3}, {%4,%5,%6,%7}, {%8,%9}, {%0,%1,%2,%3};"
        : "+f"(c[0]), "+f"(c[1]), "+f"(c[2]), "+f"(c[3])
        : "r"(a[0]), "r"(a[1]), "r"(a[2]), "r"(a[3]), "r"(b0), "r"(b1));
}

// ---------------- prep: W -> Wt[tap][co][ci_perm] ----------------
__global__ void prep_w_kernel(const float* __restrict__ W) {
    int idx = blockIdx.x * 256 + threadIdx.x;
    if (idx >= 9 * 128 * 128) return;
    int tap = idx >> 14;
    int co  = (idx >> 7) & 127;
    int ci  = idx & 127;
    uint32_t p = pack_hl(W[co * 1152 + ci * 9 + tap]);
    Wt[tap][co][(ci >> 4) * 16 + slot16(ci & 15)] = p;
}

// ---------------- main ----------------
__global__ void __launch_bounds__(512, 1)
kagome_mma_kernel(const float* __restrict__ x,
                  const float* __restrict__ b,
                  float* __restrict__ out) {
    extern __shared__ uint32_t xp2[];   // [324 pos][PAD]; data in first 128 u32

    const int tid   = threadIdx.x;
    const int wid   = tid >> 5;
    const int lane  = tid & 31;
    const int q     = lane & 3;
    const int lr    = lane >> 2;
    const int warpM = wid & 3;
    const int warpN = wid >> 2;
    const int img   = blockIdx.x;

    const float* xg = x + (size_t)img * 128 * 256;

    // ---- zero the 68-cell pad ring only (interior fully overwritten) ----
    for (int j = tid; j < 68 * 32; j += 512) {
        int ri = j >> 5, ch = j & 31;        // ring index, 16B chunk
        int pos;
        if (ri < 18)       pos = ri;                      // row 0
        else if (ri < 36)  pos = 17 * 18 + (ri - 18);     // row 17
        else if (ri < 52)  pos = (ri - 35) * 18;          // col 0, rows 1..16
        else               pos = (ri - 51) * 18 + 17;     // col 17, rows 1..16
        *(uint4*)(xp2 + pos * PAD + ch * 4) = make_uint4(0, 0, 0, 0);
    }
    // no sync needed yet: ring cells are disjoint from interior writes
    #pragma unroll
    for (int i = 0; i < 64; i++) {
        int idx = tid + i * 512;             // = ci*256 + px
        int ci = idx >> 8, px = idx & 255;
        uint32_t p = pack_hl(xg[idx]);
        int pos = ((px >> 4) + 1) * 18 + (px & 15) + 1;
        xp2[pos * PAD + (ci >> 4) * 16 + slot16(ci & 15)] = p;
    }
    __syncthreads();   // interior visible before fixups overwrite
    for (int j = tid; j < 128 * 37; j += 512) {
        int ci = j / 37, f = j - ci * 37;
        uint32_t p = pack_hl(xg[ci * 256 + (FSR[f] - 1) * 16 + (FSC[f] - 1)]);
        int pos = FDR[f] * 18 + FDC[f];
        xp2[pos * PAD + (ci >> 4) * 16 + slot16(ci & 15)] = p;
    }
    __syncthreads();

    // ---- mainloop ----
    float C[4][4][4];
    #pragma unroll
    for (int s = 0; s < 4; s++)
        #pragma unroll
        for (int n = 0; n < 4; n++)
            #pragma unroll
            for (int e = 0; e < 4; e++) C[s][n][e] = 0.f;

    for (int tap = 0; tap < 9; tap++) {
        const int kr = tap / 3, kc = tap - kr * 3;
        #pragma unroll
        for (int g = 0; g < 8; g++) {
            // --- B fragments for all 4 ns, resident (hoisted LDGs) ---
            uint32_t bh[4][2], bl[4][2];
            #pragma unroll
            for (int ns = 0; ns < 4; ns++) {
                int co = warpN * 32 + ns * 8 + lr;
                uint4 w = __ldg((const uint4*)&Wt[tap][co][g * 16 + q * 4]);
                bh[ns][0] = __byte_perm(w.x, w.y, 0x5410);
                bh[ns][1] = __byte_perm(w.z, w.w, 0x5410);
                bl[ns][0] = __byte_perm(w.x, w.y, 0x7632);
                bl[ns][1] = __byte_perm(w.z, w.w, 0x7632);
            }
            // --- s processed in halves of 2; pass-major mma order ---
            #pragma unroll
            for (int sh = 0; sh < 2; sh++) {
                uint32_t ah[2][4], al[2][4];
                #pragma unroll
                for (int s2 = 0; s2 < 2; s2++) {
                    int R = warpM * 4 + sh * 2 + s2;
                    int base = ((R + kr) * 18 + kc) * PAD + g * 16 + q * 4;
                    uint4 v0 = *(const uint4*)(xp2 + base + lr * PAD);
                    uint4 v1 = *(const uint4*)(xp2 + base + (lr + 8) * PAD);
                    ah[s2][0] = __byte_perm(v0.x, v0.y, 0x5410);
                    ah[s2][2] = __byte_perm(v0.z, v0.w, 0x5410);
                    ah[s2][1] = __byte_perm(v1.x, v1.y, 0x5410);
                    ah[s2][3] = __byte_perm(v1.z, v1.w, 0x5410);
                    al[s2][0] = __byte_perm(v0.x, v0.y, 0x7632);
                    al[s2][2] = __byte_perm(v0.z, v0.w, 0x7632);
                    al[s2][1] = __byte_perm(v1.x, v1.y, 0x7632);
                    al[s2][3] = __byte_perm(v1.z, v1.w, 0x7632);
                }
                // pass 1: hh  (same-C reuse distance = 8 mma)
                #pragma unroll
                for (int ns = 0; ns < 4; ns++)
                    #pragma unroll
                    for (int s2 = 0; s2 < 2; s2++)
                        mma_bf16(C[sh * 2 + s2][ns], ah[s2], bh[ns][0], bh[ns][1]);
                // pass 2: lh
                #pragma unroll
                for (int ns = 0; ns < 4; ns++)
                    #pragma unroll
                    for (int s2 = 0; s2 < 2; s2++)
                        mma_bf16(C[sh * 2 + s2][ns], al[s2], bh[ns][0], bh[ns][1]);
                // pass 3: hl
                #pragma unroll
                for (int ns = 0; ns < 4; ns++)
                    #pragma unroll
                    for (int s2 = 0; s2 < 2; s2++)
                        mma_bf16(C[sh * 2 + s2][ns], ah[s2], bl[ns][0], bl[ns][1]);
            }
        }
    }

    // ---- epilogue: +bias, *mask, store ----
    float* og = out + (size_t)img * 128 * 256;
    #pragma unroll
    for (int ns = 0; ns < 4; ns++) {
        int co0 = warpN * 32 + ns * 8 + 2 * q;
        float bv0 = __ldg(b + co0);
        float bv1 = __ldg(b + co0 + 1);
        #pragma unroll
        for (int s = 0; s < 4; s++) {
            int R = warpM * 4 + s;
            unsigned mrow = MASKROW[R];
            float k0 = ((mrow >> lr) & 1u) ? 1.f : 0.f;
            float k1 = ((mrow >> (lr + 8)) & 1u) ? 1.f : 0.f;
            int p0 = R * 16 + lr;
            int p1 = p0 + 8;
            og[co0 * 256 + p0]       = (C[s][ns][0] + bv0) * k0;
            og[(co0 + 1) * 256 + p0] = (C[s][ns][1] + bv1) * k0;
            og[co0 * 256 + p1]       = (C[s][ns][2] + bv0) * k1;
            og[(co0 + 1) * 256 + p1] = (C[s][ns][3] + bv1) * k1;
        }
    }
}

extern "C" void kernel_launch(void* const* d_in, const int* in_sizes, int n_in,
                              void* d_out, int out_size) {
    (void)in_sizes; (void)n_in; (void)out_size;
    const float* x = (const float*)d_in[0];
    const float* W = (const float*)d_in[1];
    const float* b = (const float*)d_in[2];
    float* out = (float*)d_out;

    cudaFuncSetAttribute(kagome_mma_kernel,
                         cudaFuncAttributeMaxDynamicSharedMemorySize, SMEM_BYTES);

    prep_w_kernel<<<(9 * 128 * 128 + 255) / 256, 256>>>(W);
    kagome_mma_kernel<<<2048, 512, SMEM_BYTES>>>(x, b, out);
}

// round 8
// speedup vs baseline: 1.9748x; 1.8431x over previous
#include <cuda_runtime.h>
#include <cuda_fp16.h>
#include <cstdint>

// ===========================================================================
// Kagome conv as implicit GEMM, fp16 SINGLE-PASS mma.sync (fp32 accum).
// R8: 3x fewer mma than the bf16 hi/lo 3-pass (R4-R7 all showed elapsed ~=
// tensor-work + L1-work with poor overlap; only reducing both helps).
//   - A: smem transposed [ci-pair][pos] u32 = half2 -> 4 raw LDS.32 per
//     m-subtile, conflict-free (stride 328 == 8 mod 32), no byte_perms
//   - B: W prepacked [tap][g][warpN][lr][kq][ns] -> 2 coalesced LDG.128
//     per g-iter, register double-buffer with prefetch distance 2
// Precision: fp16 rounding of A/B -> norm rel_err ~1e-4 (threshold 1e-3).
// ===========================================================================

__constant__ int FDR[37] = {1,1,2,3,4,4,6,7,8,10,11,12,14,14,15,16,17,17,16,15,14,14,12,10,8,6,4,4,3,2,5,9,13,15,17,15,13};
__constant__ int FDC[37] = {3,5,7,9,10,11,13,13,14,15,15,16,15,16,15,14,13,11,9,7,6,5,3,2,1,0,0,1,1,2,0,2,4,8,12,14,16};
__constant__ int FSR[37] = {13,13,14,15,16,16,6,7,8,10,11,12,2,2,3,4,5,5,4,3,2,2,12,10,8,6,16,16,15,14,5,9,1,3,5,3,1};
__constant__ int FSC[37] = {15,5,7,9,10,11,1,1,2,3,3,4,3,4,3,2,1,11,9,7,6,5,15,14,13,12,12,13,13,14,12,14,4,8,12,2,4};

__constant__ unsigned MASKROW[16] = {
    0x0008u, 0x003Cu, 0x00FEu, 0x01FEu,
    0x0FFFu, 0x0FFFu, 0x0FFFu, 0x1FFEu,
    0x3FFCu, 0x3FFCu, 0x3FFCu, 0x7FF8u,
    0x7FF0u, 0x3FC0u, 0x1F00u, 0x1E00u
};

// W packed: index = ((((tap*8+g)*4+wn)*8+lr)*8+kq)*4+ns ; u32 = half2(ci, ci+1)
// with co = wn*32+ns*8+lr, ci = g*16+2*kq.
__device__ unsigned int Wf[9 * 8 * 4 * 8 * 8 * 4];   // 73728 u32

#define PSTR 328                      // pos stride (u32); 328%32==8
#define SMEM_BYTES (64 * PSTR * 4)    // 83,968 B

static __device__ __forceinline__ uint32_t packh2(float a, float b) {
    __half2 h = __floats2half2_rn(a, b);   // a -> low half (k), b -> high (k+1)
    return *reinterpret_cast<uint32_t*>(&h);
}

static __device__ __forceinline__ void mma_fp16(float* c, const uint32_t* a,
                                                uint32_t b0, uint32_t b1) {
    asm volatile(
        "mma.sync.aligned.m16n8k16.row.col.f32.f16.f16.f32 "
        "{%0,%1,%2,%3}, {%4,%5,%6,%7}, {%8,%9}, {%0,%1,%2,%3};"
        : "+f"(c[0]), "+f"(c[1]), "+f"(c[2]), "+f"(c[3])
        : "r"(a[0]), "r"(a[1]), "r"(a[2]), "r"(a[3]), "r"(b0), "r"(b1));
}

// ---------------- prep: W -> Wf ----------------
__global__ void prep_w_kernel(const float* __restrict__ W) {
    int idx = blockIdx.x * 256 + threadIdx.x;
    if (idx >= 73728) return;
    int ns  = idx & 3;
    int kq  = (idx >> 2) & 7;
    int lr  = (idx >> 5) & 7;
    int wn  = (idx >> 8) & 3;
    int g   = (idx >> 10) & 7;
    int tap = idx >> 13;
    int co  = wn * 32 + ns * 8 + lr;
    int ci  = g * 16 + kq * 2;
    Wf[idx] = packh2(W[co * 1152 + ci * 9 + tap],
                     W[co * 1152 + (ci + 1) * 9 + tap]);
}

// ---------------- main ----------------
__global__ void __launch_bounds__(512, 1)
kagome_mma_kernel(const float* __restrict__ x,
                  const float* __restrict__ b,
                  float* __restrict__ out) {
    extern __shared__ uint32_t xph[];   // [64 ci-pair][PSTR pos]

    const int tid   = threadIdx.x;
    const int wid   = tid >> 5;
    const int lane  = tid & 31;
    const int q     = lane & 3;
    const int lr    = lane >> 2;
    const int warpM = wid & 3;
    const int warpN = wid >> 2;
    const int img   = blockIdx.x;

    const float* xg = x + (size_t)img * 128 * 256;

    // ---- zero whole tile (borders must be 0) ----
    {
        uint4* z = (uint4*)xph;
        for (int j = tid; j < 64 * PSTR / 4; j += 512)
            z[j] = make_uint4(0, 0, 0, 0);
    }
    __syncthreads();
    // ---- interior: (pair p, px quad) ----
    #pragma unroll
    for (int i = 0; i < 8; i++) {
        int idx = tid + i * 512;            // 0..4095
        int p   = idx >> 6;                 // ci pair 0..63
        int px4 = (idx & 63) << 2;          // 0,4,...,252
        float4 r0 = *(const float4*)(xg + (2 * p) * 256 + px4);
        float4 r1 = *(const float4*)(xg + (2 * p + 1) * 256 + px4);
        int pos = ((px4 >> 4) + 1) * 18 + (px4 & 15) + 1;   // cols within a row
        uint32_t* d = xph + p * PSTR + pos;
        d[0] = packh2(r0.x, r1.x);
        d[1] = packh2(r0.y, r1.y);
        d[2] = packh2(r0.z, r1.z);
        d[3] = packh2(r0.w, r1.w);
    }
    __syncthreads();   // interior visible before fixups overwrite
    // ---- 37 boundary fixups per ci pair (gather from gmem x) ----
    for (int j = tid; j < 64 * 37; j += 512) {
        int p = j / 37, f = j - p * 37;
        int spx = (FSR[f] - 1) * 16 + (FSC[f] - 1);
        uint32_t v = packh2(xg[(2 * p) * 256 + spx], xg[(2 * p + 1) * 256 + spx]);
        xph[p * PSTR + FDR[f] * 18 + FDC[f]] = v;
    }
    __syncthreads();

    // ---- mainloop: 72 iterations (9 taps x 8 ci-groups) ----
    float C[4][4][4];
    #pragma unroll
    for (int s = 0; s < 4; s++)
        #pragma unroll
        for (int n = 0; n < 4; n++)
            #pragma unroll
            for (int e = 0; e < 4; e++) C[s][n][e] = 0.f;

    const uint32_t* wbase = Wf + ((warpN * 8) + lr) * 32 + q * 4;
    // register double-buffer, prefetch distance 2 (u advances by 1024 u32)
    uint4 Bs[2][2];
    Bs[0][0] = __ldg((const uint4*)(wbase));
    Bs[0][1] = __ldg((const uint4*)(wbase + 16));
    Bs[1][0] = __ldg((const uint4*)(wbase + 1024));
    Bs[1][1] = __ldg((const uint4*)(wbase + 1024 + 16));

    #pragma unroll 1
    for (int u = 0; u < 72; u++) {
        const int tap = u >> 3, g = u & 7;
        const int kr = tap / 3, kc = tap - kr * 3;

        uint4 b0 = Bs[u & 1][0];
        uint4 b1 = Bs[u & 1][1];
        if (u < 70) {
            const uint32_t* wp = wbase + (u + 2) * 1024;
            Bs[u & 1][0] = __ldg((const uint4*)(wp));
            Bs[u & 1][1] = __ldg((const uint4*)(wp + 16));
        }

        const uint32_t* aslot = xph + (g * 8 + q) * PSTR;
        #pragma unroll
        for (int s = 0; s < 4; s++) {
            int R = warpM * 4 + s;
            int pos = (R + kr) * 18 + lr + kc;
            uint32_t A[4];
            A[0] = aslot[pos];                 // m=lr,   k 2q,2q+1
            A[1] = aslot[pos + 8];             // m=lr+8, k 2q,2q+1
            A[2] = aslot[4 * PSTR + pos];      // m=lr,   k 2q+8,2q+9
            A[3] = aslot[4 * PSTR + pos + 8];  // m=lr+8, k 2q+8,2q+9
            mma_fp16(C[s][0], A, b0.x, b1.x);
            mma_fp16(C[s][1], A, b0.y, b1.y);
            mma_fp16(C[s][2], A, b0.z, b1.z);
            mma_fp16(C[s][3], A, b0.w, b1.w);
        }
    }

    // ---- epilogue: +bias, *mask, store ----
    float* og = out + (size_t)img * 128 * 256;
    #pragma unroll
    for (int ns = 0; ns < 4; ns++) {
        int co0 = warpN * 32 + ns * 8 + 2 * q;
        float bv0 = __ldg(b + co0);
        float bv1 = __ldg(b + co0 + 1);
        #pragma unroll
        for (int s = 0; s < 4; s++) {
            int R = warpM * 4 + s;
            unsigned mrow = MASKROW[R];
            float k0 = ((mrow >> lr) & 1u) ? 1.f : 0.f;
            float k1 = ((mrow >> (lr + 8)) & 1u) ? 1.f : 0.f;
            int p0 = R * 16 + lr;
            int p1 = p0 + 8;
            og[co0 * 256 + p0]       = (C[s][ns][0] + bv0) * k0;
            og[(co0 + 1) * 256 + p0] = (C[s][ns][1] + bv1) * k0;
            og[co0 * 256 + p1]       = (C[s][ns][2] + bv0) * k1;
            og[(co0 + 1) * 256 + p1] = (C[s][ns][3] + bv1) * k1;
        }
    }
}

extern "C" void kernel_launch(void* const* d_in, const int* in_sizes, int n_in,
                              void* d_out, int out_size) {
    (void)in_sizes; (void)n_in; (void)out_size;
    const float* x = (const float*)d_in[0];
    const float* W = (const float*)d_in[1];
    const float* b = (const float*)d_in[2];
    float* out = (float*)d_out;

    cudaFuncSetAttribute(kagome_mma_kernel,
                         cudaFuncAttributeMaxDynamicSharedMemorySize, SMEM_BYTES);

    prep_w_kernel<<<288, 256>>>(W);
    kagome_mma_kernel<<<2048, 512, SMEM_BYTES>>>(x, b, out);
}